// round 15
// baseline (speedup 1.0000x reference)
#include <cuda_runtime.h>
#include <cuda_fp16.h>
#include <cstdint>

#define SEQ 2048
#define HD  64
#define BM  128
#define BN  64
#define NT  128
#define NTILES (SEQ / BN)
#define BH  32
#define PSC 0.125f
#define QJL 0.01f
#define QSCALE 0.18033688011112042f   // (1/8) * log2(e)

#define TILE_B 8192                    // one K or V tile: 64 rows x 128B swizzled
#define BUF_B  (2 * TILE_B)
#define SMEM_BYTES (2 * BUF_B)         // 32768 (Q staging = 32KB fits exactly)

__device__ __half g_kd[BH * SEQ * HD];
__device__ __half g_vd[BH * SEQ * HD];

__device__ __forceinline__ uint32_t h2u(__half2 h) { return *reinterpret_cast<uint32_t*>(&h); }
__device__ __forceinline__ __half2 u2h(uint32_t u) { return *reinterpret_cast<__half2*>(&u); }

__device__ __forceinline__ uint32_t ex2h2(uint32_t x) {
    uint32_t r; asm("ex2.approx.f16x2 %0, %1;" : "=r"(r) : "r"(x)); return r;
}
__device__ __forceinline__ void mma_f16(float* d, const uint32_t* a,
                                        uint32_t b0, uint32_t b1) {
    asm volatile(
        "mma.sync.aligned.m16n8k16.row.col.f32.f16.f16.f32 "
        "{%0,%1,%2,%3}, {%4,%5,%6,%7}, {%8,%9}, {%0,%1,%2,%3};"
        : "+f"(d[0]), "+f"(d[1]), "+f"(d[2]), "+f"(d[3])
        : "r"(a[0]), "r"(a[1]), "r"(a[2]), "r"(a[3]), "r"(b0), "r"(b1));
}
__device__ __forceinline__ void ldsm4(uint32_t& r0, uint32_t& r1, uint32_t& r2,
                                      uint32_t& r3, uint32_t a) {
    asm volatile("ldmatrix.sync.aligned.m8n8.x4.shared.b16 {%0,%1,%2,%3}, [%4];"
                 : "=r"(r0), "=r"(r1), "=r"(r2), "=r"(r3) : "r"(a));
}
__device__ __forceinline__ void ldsm4t(uint32_t& r0, uint32_t& r1, uint32_t& r2,
                                       uint32_t& r3, uint32_t a) {
    asm volatile("ldmatrix.sync.aligned.m8n8.x4.trans.shared.b16 {%0,%1,%2,%3}, [%4];"
                 : "=r"(r0), "=r"(r1), "=r"(r2), "=r"(r3) : "r"(a));
}
__device__ __forceinline__ uint32_t smem_u32(const void* p) {
    uint32_t a;
    asm("{ .reg .u64 t; cvta.to.shared.u64 t, %1; cvt.u32.u64 %0, t; }" : "=r"(a) : "l"(p));
    return a;
}
__device__ __forceinline__ void cp16(uint32_t dst, const void* src) {
    asm volatile("cp.async.cg.shared.global [%0], [%1], 16;" :: "r"(dst), "l"(src));
}

// ---- pre-pass: pure streaming dequant (unchanged) ----
__global__ void __launch_bounds__(256) deq_kv(
    const float* __restrict__ kp, const float* __restrict__ kq,
    const float* __restrict__ vp, const float* __restrict__ vq)
{
    size_t i = ((size_t)blockIdx.x * 256 + threadIdx.x) * 8;

    float4 a0 = *reinterpret_cast<const float4*>(kp + i);
    float4 a1 = *reinterpret_cast<const float4*>(kp + i + 4);
    float4 b0 = *reinterpret_cast<const float4*>(kq + i);
    float4 b1 = *reinterpret_cast<const float4*>(kq + i + 4);
    uint4 w;
    w.x = h2u(__floats2half2_rn(a0.x * PSC + b0.x * QJL, a0.y * PSC + b0.y * QJL));
    w.y = h2u(__floats2half2_rn(a0.z * PSC + b0.z * QJL, a0.w * PSC + b0.w * QJL));
    w.z = h2u(__floats2half2_rn(a1.x * PSC + b1.x * QJL, a1.y * PSC + b1.y * QJL));
    w.w = h2u(__floats2half2_rn(a1.z * PSC + b1.z * QJL, a1.w * PSC + b1.w * QJL));
    *reinterpret_cast<uint4*>(g_kd + i) = w;

    a0 = *reinterpret_cast<const float4*>(vp + i);
    a1 = *reinterpret_cast<const float4*>(vp + i + 4);
    b0 = *reinterpret_cast<const float4*>(vq + i);
    b1 = *reinterpret_cast<const float4*>(vq + i + 4);
    w.x = h2u(__floats2half2_rn(a0.x * PSC + b0.x * QJL, a0.y * PSC + b0.y * QJL));
    w.y = h2u(__floats2half2_rn(a0.z * PSC + b0.z * QJL, a0.w * PSC + b0.w * QJL));
    w.z = h2u(__floats2half2_rn(a1.x * PSC + b1.x * QJL, a1.y * PSC + b1.y * QJL));
    w.w = h2u(__floats2half2_rn(a1.z * PSC + b1.z * QJL, a1.w * PSC + b1.w * QJL));
    *reinterpret_cast<uint4*>(g_vd + i) = w;
}

// ---- attention: BM=128, n-split halves to cap registers ----
__global__ void __launch_bounds__(NT, 3) tq_attn_mma(
    const float* __restrict__ q, float* __restrict__ out)
{
    extern __shared__ char dsm[];
    const uint32_t sb = smem_u32(dsm);

    const int tid  = threadIdx.x;
    const int lane = tid & 31;
    const int g    = lane >> 2;
    const int t    = lane & 3;
    const int wrow = (tid >> 5) * 32;    // warp owns 32 Q rows (2 m-fragments)

    const int    m0   = blockIdx.x * BM;
    const int    bh   = blockIdx.y;
    const size_t base = (size_t)bh * (size_t)(SEQ * HD);

    // ---- stage Q (128 rows x 64 fp32 = 32KB) ----
    {
        float* sQ = reinterpret_cast<float*>(dsm);
        #pragma unroll
        for (int it = 0; it < 16; ++it) {
            int idx = tid + it * NT;
            int r = idx >> 4, c4 = idx & 15;
            float4 v = *reinterpret_cast<const float4*>(
                q + base + (size_t)(m0 + r) * HD + c4 * 4);
            *reinterpret_cast<float4*>(&sQ[r * HD + c4 * 4]) = v;
        }
    }
    __syncthreads();
    uint32_t qa[2][4][4];
    #pragma unroll
    for (int mf = 0; mf < 2; ++mf) {
        const float* q0 = reinterpret_cast<float*>(dsm) + (wrow + mf * 16 + g) * HD + 2 * t;
        const float* q8 = q0 + 8 * HD;
        #pragma unroll
        for (int kc2 = 0; kc2 < 4; ++kc2) {
            int c = kc2 * 16;
            qa[mf][kc2][0] = h2u(__floats2half2_rn(QSCALE * q0[c],     QSCALE * q0[c + 1]));
            qa[mf][kc2][1] = h2u(__floats2half2_rn(QSCALE * q8[c],     QSCALE * q8[c + 1]));
            qa[mf][kc2][2] = h2u(__floats2half2_rn(QSCALE * q0[c + 8], QSCALE * q0[c + 9]));
            qa[mf][kc2][3] = h2u(__floats2half2_rn(QSCALE * q8[c + 8], QSCALE * q8[c + 9]));
        }
    }
    __syncthreads();

    const char* kgm = reinterpret_cast<const char*>(g_kd) + (size_t)bh * SEQ * HD * 2;
    const char* vgm = reinterpret_cast<const char*>(g_vd) + (size_t)bh * SEQ * HD * 2;

    // ---- prologue: async-load tile 0 ----
    #pragma unroll
    for (int it = 0; it < 4; ++it) {
        int part = tid + it * NT;
        uint32_t r = part >> 3, c = part & 7;
        uint32_t woff = r * 128 + ((c ^ (r & 7)) << 4);
        cp16(sb + woff, kgm + part * 16);
        cp16(sb + TILE_B + woff, vgm + part * 16);
    }
    asm volatile("cp.async.commit_group;" ::: "memory");

    const uint32_t l7     = lane & 7;
    const uint32_t krbase = ((((uint32_t)lane >> 4) & 1) * 8 + l7) * 128;
    const uint32_t kcbit  = ((uint32_t)lane >> 3) & 1;
    const uint32_t vrbase = ((((uint32_t)lane >> 3) & 1) * 8 + l7) * 128;
    const uint32_t vcbit  = ((uint32_t)lane >> 4) & 1;

    float o[2][8][4];
    #pragma unroll
    for (int mf = 0; mf < 2; ++mf)
        #pragma unroll
        for (int i = 0; i < 8; ++i)
            #pragma unroll
            for (int j = 0; j < 4; ++j) o[mf][i][j] = 0.f;
    float rsum[2][2] = {{0.f, 0.f}, {0.f, 0.f}};

    for (int tl = 0; tl < NTILES; ++tl) {
        if (tl + 1 < NTILES) {
            const uint32_t nb = sb + ((tl + 1) & 1) * BUF_B;
            const char* ks = kgm + (size_t)(tl + 1) * TILE_B;
            const char* vs = vgm + (size_t)(tl + 1) * TILE_B;
            #pragma unroll
            for (int it = 0; it < 4; ++it) {
                int part = tid + it * NT;
                uint32_t r = part >> 3, c = part & 7;
                uint32_t woff = r * 128 + ((c ^ (r & 7)) << 4);
                cp16(nb + woff, ks + part * 16);
                cp16(nb + TILE_B + woff, vs + part * 16);
            }
            asm volatile("cp.async.commit_group;" ::: "memory");
            asm volatile("cp.async.wait_group 1;" ::: "memory");
        } else {
            asm volatile("cp.async.wait_group 0;" ::: "memory");
        }
        __syncthreads();

        const uint32_t bufK = sb + (tl & 1) * BUF_B;
        const uint32_t bufV = bufK + TILE_B;

        __half2 hacc[2][2];
        hacc[0][0] = u2h(0u); hacc[0][1] = u2h(0u);
        hacc[1][0] = u2h(0u); hacc[1][1] = u2h(0u);

        // ---- two n-halves: QK(half) -> softmax(half) -> PV(half) ----
        #pragma unroll
        for (int nh = 0; nh < 2; ++nh) {
            float s[2][4][4];
            #pragma unroll
            for (int mf = 0; mf < 2; ++mf)
                #pragma unroll
                for (int i = 0; i < 4; ++i)
                    #pragma unroll
                    for (int j = 0; j < 4; ++j) s[mf][i][j] = 0.f;

            #pragma unroll
            for (int kc2 = 0; kc2 < 4; ++kc2) {
                #pragma unroll
                for (int np = 0; np < 2; ++np) {
                    int ntp = nh * 2 + np;
                    uint32_t addr = bufK + (uint32_t)(ntp * 16 * 128) + krbase
                                  + ((((uint32_t)(2 * kc2) + kcbit) ^ l7) << 4);
                    uint32_t b0, b1, b2, b3;
                    ldsm4(b0, b1, b2, b3, addr);
                    mma_f16(s[0][2 * np],     qa[0][kc2], b0, b1);
                    mma_f16(s[0][2 * np + 1], qa[0][kc2], b2, b3);
                    mma_f16(s[1][2 * np],     qa[1][kc2], b0, b1);
                    mma_f16(s[1][2 * np + 1], qa[1][kc2], b2, b3);
                }
            }

            #pragma unroll
            for (int kh = 0; kh < 2; ++kh) {          // global n-chunk = nh*2+kh
                uint32_t pa[2][4];
                #pragma unroll
                for (int mf = 0; mf < 2; ++mf) {
                    pa[mf][0] = ex2h2(h2u(__floats2half2_rn(s[mf][2 * kh][0],     s[mf][2 * kh][1])));
                    pa[mf][1] = ex2h2(h2u(__floats2half2_rn(s[mf][2 * kh][2],     s[mf][2 * kh][3])));
                    pa[mf][2] = ex2h2(h2u(__floats2half2_rn(s[mf][2 * kh + 1][0], s[mf][2 * kh + 1][1])));
                    pa[mf][3] = ex2h2(h2u(__floats2half2_rn(s[mf][2 * kh + 1][2], s[mf][2 * kh + 1][3])));
                    hacc[mf][0] = __hadd2(hacc[mf][0], __hadd2(u2h(pa[mf][0]), u2h(pa[mf][2])));
                    hacc[mf][1] = __hadd2(hacc[mf][1], __hadd2(u2h(pa[mf][1]), u2h(pa[mf][3])));
                }
                int kc2g = nh * 2 + kh;
                #pragma unroll
                for (int dtp = 0; dtp < 4; ++dtp) {
                    uint32_t addr = bufV + (uint32_t)(kc2g * 16 * 128) + vrbase
                                  + ((((uint32_t)(2 * dtp) + vcbit) ^ l7) << 4);
                    uint32_t v0, v1, v2, v3;
                    ldsm4t(v0, v1, v2, v3, addr);
                    mma_f16(o[0][2 * dtp],     pa[0], v0, v1);
                    mma_f16(o[0][2 * dtp + 1], pa[0], v2, v3);
                    mma_f16(o[1][2 * dtp],     pa[1], v0, v1);
                    mma_f16(o[1][2 * dtp + 1], pa[1], v2, v3);
                }
            }
        }

        #pragma unroll
        for (int mf = 0; mf < 2; ++mf) {
            float2 f0 = __half22float2(hacc[mf][0]);
            float2 f1 = __half22float2(hacc[mf][1]);
            rsum[mf][0] += f0.x + f0.y;
            rsum[mf][1] += f1.x + f1.y;
        }
        __syncthreads();
    }

    // ---- epilogue ----
    #pragma unroll
    for (int mf = 0; mf < 2; ++mf) {
        float r0s = rsum[mf][0], r1s = rsum[mf][1];
        r0s += __shfl_xor_sync(0xffffffffu, r0s, 1);
        r0s += __shfl_xor_sync(0xffffffffu, r0s, 2);
        r1s += __shfl_xor_sync(0xffffffffu, r1s, 1);
        r1s += __shfl_xor_sync(0xffffffffu, r1s, 2);
        const float inv0 = 1.0f / r0s;
        const float inv1 = 1.0f / r1s;

        const size_t row0 = base + (size_t)(m0 + wrow + mf * 16 + g) * HD;
        const size_t row1 = row0 + 8 * HD;
        #pragma unroll
        for (int dt = 0; dt < 8; ++dt) {
            float2 w0 = make_float2(o[mf][dt][0] * inv0, o[mf][dt][1] * inv0);
            float2 w1 = make_float2(o[mf][dt][2] * inv1, o[mf][dt][3] * inv1);
            *reinterpret_cast<float2*>(out + row0 + dt * 8 + 2 * t) = w0;
            *reinterpret_cast<float2*>(out + row1 + dt * 8 + 2 * t) = w1;
        }
    }
}

extern "C" void kernel_launch(void* const* d_in, const int* in_sizes, int n_in,
                              void* d_out, int out_size)
{
    const float* q  = (const float*)d_in[0];
    const float* kp = (const float*)d_in[1];
    const float* kq = (const float*)d_in[2];
    const float* vp = (const float*)d_in[3];
    const float* vq = (const float*)d_in[4];
    float* out = (float*)d_out;

    static int cfg_done = 0;
    if (!cfg_done) {
        cudaFuncSetAttribute(tq_attn_mma,
                             cudaFuncAttributeMaxDynamicSharedMemorySize, SMEM_BYTES);
        cfg_done = 1;
    }

    deq_kv<<<(BH * SEQ * HD) / (8 * 256), 256>>>(kp, kq, vp, vq);

    dim3 grid(SEQ / BM, BH);
    tq_attn_mma<<<grid, NT, SMEM_BYTES>>>(q, out);
}

// round 17
// speedup vs baseline: 1.1127x; 1.1127x over previous
#include <cuda_runtime.h>
#include <cuda_fp16.h>
#include <cstdint>

#define SEQ 2048
#define HD  64
#define BM  64
#define BN  64
#define NT  128
#define NTILES (SEQ / BN)
#define BH  32
#define PSC 0.125f
#define QJL 0.01f
#define QSCALE 0.18033688011112042f   // (1/8) * log2(e)

#define TILE_B 8192                    // one K or V tile: 64 rows x 128B swizzled
#define BUF_B  (2 * TILE_B)            // K + V per stage = 16384
#define NBUF 3
#define SMEM_BYTES (NBUF * BUF_B)      // 49152 -> 4 CTAs/SM

__device__ __half g_kd[BH * SEQ * HD];
__device__ __half g_vd[BH * SEQ * HD];

__device__ __forceinline__ uint32_t h2u(__half2 h) { return *reinterpret_cast<uint32_t*>(&h); }
__device__ __forceinline__ __half2 u2h(uint32_t u) { return *reinterpret_cast<__half2*>(&u); }

__device__ __forceinline__ uint32_t ex2h2(uint32_t x) {
    uint32_t r; asm("ex2.approx.f16x2 %0, %1;" : "=r"(r) : "r"(x)); return r;
}
__device__ __forceinline__ void mma_f16(float* d, const uint32_t* a,
                                        uint32_t b0, uint32_t b1) {
    asm volatile(
        "mma.sync.aligned.m16n8k16.row.col.f32.f16.f16.f32 "
        "{%0,%1,%2,%3}, {%4,%5,%6,%7}, {%8,%9}, {%0,%1,%2,%3};"
        : "+f"(d[0]), "+f"(d[1]), "+f"(d[2]), "+f"(d[3])
        : "r"(a[0]), "r"(a[1]), "r"(a[2]), "r"(a[3]), "r"(b0), "r"(b1));
}
__device__ __forceinline__ void ldsm4(uint32_t& r0, uint32_t& r1, uint32_t& r2,
                                      uint32_t& r3, uint32_t a) {
    asm volatile("ldmatrix.sync.aligned.m8n8.x4.shared.b16 {%0,%1,%2,%3}, [%4];"
                 : "=r"(r0), "=r"(r1), "=r"(r2), "=r"(r3) : "r"(a));
}
__device__ __forceinline__ void ldsm4t(uint32_t& r0, uint32_t& r1, uint32_t& r2,
                                       uint32_t& r3, uint32_t a) {
    asm volatile("ldmatrix.sync.aligned.m8n8.x4.trans.shared.b16 {%0,%1,%2,%3}, [%4];"
                 : "=r"(r0), "=r"(r1), "=r"(r2), "=r"(r3) : "r"(a));
}
__device__ __forceinline__ uint32_t smem_u32(const void* p) {
    uint32_t a;
    asm("{ .reg .u64 t; cvta.to.shared.u64 t, %1; cvt.u32.u64 %0, t; }" : "=r"(a) : "l"(p));
    return a;
}
__device__ __forceinline__ void cp16(uint32_t dst, const void* src) {
    asm volatile("cp.async.cg.shared.global [%0], [%1], 16;" :: "r"(dst), "l"(src));
}

// ---- pre-pass: pure streaming dequant (unchanged) ----
__global__ void __launch_bounds__(256) deq_kv(
    const float* __restrict__ kp, const float* __restrict__ kq,
    const float* __restrict__ vp, const float* __restrict__ vq)
{
    size_t i = ((size_t)blockIdx.x * 256 + threadIdx.x) * 8;

    float4 a0 = *reinterpret_cast<const float4*>(kp + i);
    float4 a1 = *reinterpret_cast<const float4*>(kp + i + 4);
    float4 b0 = *reinterpret_cast<const float4*>(kq + i);
    float4 b1 = *reinterpret_cast<const float4*>(kq + i + 4);
    uint4 w;
    w.x = h2u(__floats2half2_rn(a0.x * PSC + b0.x * QJL, a0.y * PSC + b0.y * QJL));
    w.y = h2u(__floats2half2_rn(a0.z * PSC + b0.z * QJL, a0.w * PSC + b0.w * QJL));
    w.z = h2u(__floats2half2_rn(a1.x * PSC + b1.x * QJL, a1.y * PSC + b1.y * QJL));
    w.w = h2u(__floats2half2_rn(a1.z * PSC + b1.z * QJL, a1.w * PSC + b1.w * QJL));
    *reinterpret_cast<uint4*>(g_kd + i) = w;

    a0 = *reinterpret_cast<const float4*>(vp + i);
    a1 = *reinterpret_cast<const float4*>(vp + i + 4);
    b0 = *reinterpret_cast<const float4*>(vq + i);
    b1 = *reinterpret_cast<const float4*>(vq + i + 4);
    w.x = h2u(__floats2half2_rn(a0.x * PSC + b0.x * QJL, a0.y * PSC + b0.y * QJL));
    w.y = h2u(__floats2half2_rn(a0.z * PSC + b0.z * QJL, a0.w * PSC + b0.w * QJL));
    w.z = h2u(__floats2half2_rn(a1.x * PSC + b1.x * QJL, a1.y * PSC + b1.y * QJL));
    w.w = h2u(__floats2half2_rn(a1.z * PSC + b1.z * QJL, a1.w * PSC + b1.w * QJL));
    *reinterpret_cast<uint4*>(g_vd + i) = w;
}

#define ISSUE_TILE(TILE, BI) do {                                        \
    const char* _ks = kgm + (size_t)(TILE) * TILE_B;                     \
    const char* _vs = vgm + (size_t)(TILE) * TILE_B;                     \
    uint32_t _bb = sb + (uint32_t)(BI) * BUF_B;                          \
    _Pragma("unroll")                                                    \
    for (int _it = 0; _it < 4; ++_it) {                                  \
        int _part = tid + _it * NT;                                      \
        uint32_t _r = _part >> 3, _c = _part & 7;                        \
        uint32_t _woff = _r * 128 + ((_c ^ (_r & 7)) << 4);              \
        cp16(_bb + _woff, _ks + _part * 16);                             \
        cp16(_bb + TILE_B + _woff, _vs + _part * 16);                    \
    }                                                                    \
    asm volatile("cp.async.commit_group;" ::: "memory");                 \
} while (0)

// ---- attention: R13 shape + 3-stage ring (wait -> sync -> issue) + n-split ----
__global__ void __launch_bounds__(NT, 4) tq_attn_mma(
    const float* __restrict__ q, float* __restrict__ out)
{
    extern __shared__ char dsm[];
    const uint32_t sb = smem_u32(dsm);

    const int tid  = threadIdx.x;
    const int lane = tid & 31;
    const int g    = lane >> 2;
    const int t    = lane & 3;
    const int wrow = (tid >> 5) * 16;

    const int    m0   = blockIdx.x * BM;
    const int    bh   = blockIdx.y;
    const size_t base = (size_t)bh * (size_t)(SEQ * HD);

    // ---- stage Q (fp32, 16KB) in buffer 0 region ----
    {
        float* sQ = reinterpret_cast<float*>(dsm);
        #pragma unroll
        for (int it = 0; it < 8; ++it) {
            int idx = tid + it * NT;
            int r = idx >> 4, c4 = idx & 15;
            float4 v = *reinterpret_cast<const float4*>(
                q + base + (size_t)(m0 + r) * HD + c4 * 4);
            *reinterpret_cast<float4*>(&sQ[r * HD + c4 * 4]) = v;
        }
    }
    __syncthreads();
    uint32_t qa[4][4];
    {
        const float* q0 = reinterpret_cast<float*>(dsm) + (wrow + g) * HD + 2 * t;
        const float* q8 = q0 + 8 * HD;
        #pragma unroll
        for (int kc2 = 0; kc2 < 4; ++kc2) {
            int c = kc2 * 16;
            qa[kc2][0] = h2u(__floats2half2_rn(QSCALE * q0[c],     QSCALE * q0[c + 1]));
            qa[kc2][1] = h2u(__floats2half2_rn(QSCALE * q8[c],     QSCALE * q8[c + 1]));
            qa[kc2][2] = h2u(__floats2half2_rn(QSCALE * q0[c + 8], QSCALE * q0[c + 9]));
            qa[kc2][3] = h2u(__floats2half2_rn(QSCALE * q8[c + 8], QSCALE * q8[c + 9]));
        }
    }
    __syncthreads();

    const char* kgm = reinterpret_cast<const char*>(g_kd) + (size_t)bh * SEQ * HD * 2;
    const char* vgm = reinterpret_cast<const char*>(g_vd) + (size_t)bh * SEQ * HD * 2;

    // ---- prologue: tiles 0 and 1 in flight ----
    ISSUE_TILE(0, 0);
    ISSUE_TILE(1, 1);

    const uint32_t l7     = lane & 7;
    const uint32_t krbase = ((((uint32_t)lane >> 4) & 1) * 8 + l7) * 128;
    const uint32_t kcbit  = ((uint32_t)lane >> 3) & 1;
    const uint32_t vrbase = ((((uint32_t)lane >> 3) & 1) * 8 + l7) * 128;
    const uint32_t vcbit  = ((uint32_t)lane >> 4) & 1;

    float o[8][4];
    #pragma unroll
    for (int i = 0; i < 8; ++i)
        #pragma unroll
        for (int j = 0; j < 4; ++j) o[i][j] = 0.f;
    float rsum0 = 0.f, rsum1 = 0.f;

    int cur = 0;
    for (int tl = 0; tl < NTILES; ++tl) {
        // wait: MY groups through tile tl retired (pending = {tl, tl+1} -> keep 1)
        if (tl < NTILES - 1) {
            asm volatile("cp.async.wait_group 1;" ::: "memory");
        } else {
            asm volatile("cp.async.wait_group 0;" ::: "memory");
        }
        // barrier: ALL threads' tile-tl data visible; all reads of tile tl-1 done
        __syncthreads();
        // issue tile tl+2 into buf[(tl+2)%3] == buf[(tl-1)%3] (reads retired pre-sync)
        if (tl + 2 < NTILES) {
            int nb = cur + 2; if (nb >= NBUF) nb -= NBUF;
            ISSUE_TILE(tl + 2, nb);
        }

        const uint32_t bufK = sb + (uint32_t)cur * BUF_B;
        const uint32_t bufV = bufK + TILE_B;

        __half2 hacc0 = u2h(0u), hacc1 = u2h(0u);

        // ---- two n-halves: QK(half) then softmax+PV(half) ----
        #pragma unroll
        for (int nh = 0; nh < 2; ++nh) {
            float s[4][4];
            #pragma unroll
            for (int i = 0; i < 4; ++i)
                #pragma unroll
                for (int j = 0; j < 4; ++j) s[i][j] = 0.f;

            #pragma unroll
            for (int kc2 = 0; kc2 < 4; ++kc2) {
                #pragma unroll
                for (int np = 0; np < 2; ++np) {
                    int ntp = nh * 2 + np;
                    uint32_t addr = bufK + (uint32_t)(ntp * 16 * 128) + krbase
                                  + ((((uint32_t)(2 * kc2) + kcbit) ^ l7) << 4);
                    uint32_t b0, b1, b2, b3;
                    ldsm4(b0, b1, b2, b3, addr);
                    mma_f16(s[2 * np],     qa[kc2], b0, b1);
                    mma_f16(s[2 * np + 1], qa[kc2], b2, b3);
                }
            }

            #pragma unroll
            for (int kh = 0; kh < 2; ++kh) {
                uint32_t pa[4];
                pa[0] = ex2h2(h2u(__floats2half2_rn(s[2 * kh][0],     s[2 * kh][1])));
                pa[1] = ex2h2(h2u(__floats2half2_rn(s[2 * kh][2],     s[2 * kh][3])));
                pa[2] = ex2h2(h2u(__floats2half2_rn(s[2 * kh + 1][0], s[2 * kh + 1][1])));
                pa[3] = ex2h2(h2u(__floats2half2_rn(s[2 * kh + 1][2], s[2 * kh + 1][3])));
                hacc0 = __hadd2(hacc0, __hadd2(u2h(pa[0]), u2h(pa[2])));
                hacc1 = __hadd2(hacc1, __hadd2(u2h(pa[1]), u2h(pa[3])));

                int kc2g = nh * 2 + kh;
                #pragma unroll
                for (int dtp = 0; dtp < 4; ++dtp) {
                    uint32_t addr = bufV + (uint32_t)(kc2g * 16 * 128) + vrbase
                                  + ((((uint32_t)(2 * dtp) + vcbit) ^ l7) << 4);
                    uint32_t v0, v1, v2, v3;
                    ldsm4t(v0, v1, v2, v3, addr);
                    mma_f16(o[2 * dtp],     pa, v0, v1);
                    mma_f16(o[2 * dtp + 1], pa, v2, v3);
                }
            }
        }

        {
            float2 f0 = __half22float2(hacc0);
            float2 f1 = __half22float2(hacc1);
            rsum0 += f0.x + f0.y;
            rsum1 += f1.x + f1.y;
        }
        ++cur; if (cur >= NBUF) cur = 0;
    }

    // ---- epilogue ----
    rsum0 += __shfl_xor_sync(0xffffffffu, rsum0, 1);
    rsum0 += __shfl_xor_sync(0xffffffffu, rsum0, 2);
    rsum1 += __shfl_xor_sync(0xffffffffu, rsum1, 1);
    rsum1 += __shfl_xor_sync(0xffffffffu, rsum1, 2);
    const float inv0 = 1.0f / rsum0;
    const float inv1 = 1.0f / rsum1;

    const size_t row0 = base + (size_t)(m0 + wrow + g) * HD;
    const size_t row1 = row0 + 8 * HD;
    #pragma unroll
    for (int dt = 0; dt < 8; ++dt) {
        float2 r0 = make_float2(o[dt][0] * inv0, o[dt][1] * inv0);
        float2 r1 = make_float2(o[dt][2] * inv1, o[dt][3] * inv1);
        *reinterpret_cast<float2*>(out + row0 + dt * 8 + 2 * t) = r0;
        *reinterpret_cast<float2*>(out + row1 + dt * 8 + 2 * t) = r1;
    }
}

extern "C" void kernel_launch(void* const* d_in, const int* in_sizes, int n_in,
                              void* d_out, int out_size)
{
    const float* q  = (const float*)d_in[0];
    const float* kp = (const float*)d_in[1];
    const float* kq = (const float*)d_in[2];
    const float* vp = (const float*)d_in[3];
    const float* vq = (const float*)d_in[4];
    float* out = (float*)d_out;

    static int cfg_done = 0;
    if (!cfg_done) {
        cudaFuncSetAttribute(tq_attn_mma,
                             cudaFuncAttributeMaxDynamicSharedMemorySize, SMEM_BYTES);
        cfg_done = 1;
    }

    deq_kv<<<(BH * SEQ * HD) / (8 * 256), 256>>>(kp, kq, vp, vq);

    dim3 grid(SEQ / BM, BH);
    tq_attn_mma<<<grid, NT, SMEM_BYTES>>>(q, out);
}